// round 4
// baseline (speedup 1.0000x reference)
#include <cuda_runtime.h>

#define C_IN   64
#define C_OUT  128
#define NKER   16
#define BEV_H  512
#define BEV_W  512
#define HW     (BEV_H * BEV_W)
#define MAXN   65536
#define NBX    1024        // (b,x) bins
#define CAPX   1024        // max points per (b,x) bin (fixed region)
#define PPB    128         // points per block, phase 1
#define ZPITCH 33          // z-major tile row pitch (floats) -> conflict-free scatter

// ---------------- scratch (__device__ globals; no allocation) ----------------
__device__ int   d_curH[NKER];
__device__ int   d_curX[NBX];
__device__ int   d_binH[NKER * MAXN];            // point index, region per h
__device__ int   d_binX[NBX * CAPX];             // packed (pt << 9) | z
__device__ float d_fbuf[(size_t)MAXN * C_OUT];   // per-point features post-GEMM

// ---------------- packed f32x2 helpers ----------------
__device__ __forceinline__ unsigned long long pack2(float lo, float hi) {
    unsigned long long r;
    asm("mov.b64 %0, {%1, %2};" : "=l"(r) : "f"(lo), "f"(hi));
    return r;
}
__device__ __forceinline__ void unpack2(unsigned long long v, float& lo, float& hi) {
    asm("mov.b64 {%0, %1}, %2;" : "=f"(lo), "=f"(hi) : "l"(v));
}
__device__ __forceinline__ unsigned long long fma2(unsigned long long a,
                                                   unsigned long long b,
                                                   unsigned long long c) {
    unsigned long long d;
    asm("fma.rn.f32x2 %0, %1, %2, %3;" : "=l"(d) : "l"(a), "l"(b), "l"(c));
    return d;
}

// ---------------------------------------------------------------------------
// Zero the bin cursors.
// ---------------------------------------------------------------------------
__global__ void k_zero() {
    int t = blockIdx.x * blockDim.x + threadIdx.x;
    if (t < NBX)  d_curX[t] = 0;
    if (t < NKER) d_curH[t] = 0;
}

// ---------------------------------------------------------------------------
// Fused binning: block-level smem histogram + rank, one global reservation
// per non-empty bin per block, then direct scatter into fixed bin regions.
// ---------------------------------------------------------------------------
__global__ __launch_bounds__(256)
void k_bin(const int* __restrict__ coords, int n)
{
    __shared__ int histH[NKER],  baseH[NKER];
    __shared__ int histX[NBX],   baseX[NBX];

    const int tid = threadIdx.x;
    for (int j = tid; j < NBX; j += 256) histX[j] = 0;
    if (tid < NKER) histH[tid] = 0;
    __syncthreads();

    int i = blockIdx.x * 256 + tid;
    int h = 0, bx = 0, z = 0, rH = 0, rX = 0;
    bool valid = (i < n);
    if (valid) {
        int4 c = ((const int4*)coords)[i];           // [x, h, z, b]
        h  = c.y & (NKER - 1);
        bx = (c.w << 9) | c.x;
        z  = c.z;
        rH = atomicAdd(&histH[h], 1);
        rX = atomicAdd(&histX[bx], 1);
    }
    __syncthreads();

    if (tid < NKER && histH[tid] > 0)
        baseH[tid] = atomicAdd(&d_curH[tid], histH[tid]);
    for (int j = tid; j < NBX; j += 256)
        if (histX[j] > 0)
            baseX[j] = atomicAdd(&d_curX[j], histX[j]);
    __syncthreads();

    if (valid) {
        d_binH[h * MAXN + baseH[h] + rH] = i;
        int slot = baseX[bx] + rX;
        if (slot < CAPX)
            d_binX[bx * CAPX + slot] = (i << 9) | z;
    }
}

// ---------------------------------------------------------------------------
// Phase 1: per-point GEMV  f_buf[pt][c] = sum_k feats[pt][k] * K[h][k][c]
// Block serves one h bin; 64x128 kernel slice staged in SMEM.
// Warp processes 4 points; lane owns 4 consecutive channels.
// Inner math on packed fma.rn.f32x2 (2 MACs / instr).
// ---------------------------------------------------------------------------
__global__ __launch_bounds__(256)
void k_feat(const float* __restrict__ feats,
            const float* __restrict__ kern)
{
    const int bin = blockIdx.y;
    const int cnt = d_curH[bin];
    const int bstart = blockIdx.x * PPB;
    if (bstart >= cnt) return;
    const int bend = min(bstart + PPB, cnt);
    const int* binp = d_binH + bin * MAXN;

    __shared__ float Ks[C_IN * C_OUT];               // 32 KB
    {
        const float4* g = (const float4*)(kern + (size_t)bin * C_IN * C_OUT);
        float4* sp = (float4*)Ks;
        for (int i = threadIdx.x; i < (C_IN * C_OUT) / 4; i += 256)
            sp[i] = g[i];
    }
    __syncthreads();

    const int warp = threadIdx.x >> 5;
    const int lane = threadIdx.x & 31;

    for (int g0 = bstart + warp * 4; g0 < bend; g0 += 32) {
        const int nv = min(4, bend - g0);
        float2 fv[4];
        int    pts[4];

        #pragma unroll
        for (int p = 0; p < 4; p++) {
            if (p < nv) {
                pts[p] = binp[g0 + p];
                fv[p]  = ((const float2*)(feats + (size_t)pts[p] * C_IN))[lane];
            } else {
                fv[p] = make_float2(0.f, 0.f);
                pts[p] = 0;
            }
        }

        unsigned long long accA[4], accB[4];
        #pragma unroll
        for (int p = 0; p < 4; p++) { accA[p] = 0ull; accB[p] = 0ull; }

        #pragma unroll
        for (int c = 0; c < C_IN; c++) {
            float4 k = *(const float4*)(Ks + c * C_OUT + 4 * lane);
            unsigned long long kA = pack2(k.x, k.y);
            unsigned long long kB = pack2(k.z, k.w);
            #pragma unroll
            for (int p = 0; p < 4; p++) {
                float f = __shfl_sync(0xffffffffu,
                                      (c & 1) ? fv[p].y : fv[p].x, c >> 1);
                unsigned long long ff = pack2(f, f);
                accA[p] = fma2(ff, kA, accA[p]);
                accB[p] = fma2(ff, kB, accB[p]);
            }
        }

        #pragma unroll
        for (int p = 0; p < 4; p++) {
            if (p < nv) {
                float4 v;
                unpack2(accA[p], v.x, v.y);
                unpack2(accB[p], v.z, v.w);
                *(float4*)(d_fbuf + (size_t)pts[p] * C_OUT + 4 * lane) = v;
            }
        }
    }
}

// ---------------------------------------------------------------------------
// Phase 2: row-owner scatter with sparse tile.
// Block = (channel group of 32, bin (b,x)). Tile is z-major [512][33] so the
// 32-lane per-point scatter (lane = channel) is bank-conflict-free.
// Pass 1 marks touched z (bitmask) and zeroes only touched cells; pass 2
// accumulates via smem atomics; readout writes register zeros for untouched
// 4-z chunks (no LDS) and reads smem only where the mask is set.
// Together the 4096 blocks overwrite every output element -> no memset.
// ---------------------------------------------------------------------------
__global__ __launch_bounds__(256)
void k_bev(float* __restrict__ out)
{
    __shared__ float tile[512 * ZPITCH];             // 67.6 KB
    __shared__ unsigned int zmask[16];               // 512 bits

    const int bin = blockIdx.y;
    const int c0  = blockIdx.x << 5;
    const int b   = bin >> 9;
    const int x   = bin & 511;
    const int tid  = threadIdx.x;
    const int warp = tid >> 5;
    const int lane = tid & 31;

    if (tid < 16) zmask[tid] = 0u;
    __syncthreads();

    int cnt = d_curX[bin];
    if (cnt > CAPX) cnt = CAPX;
    const int* binp = d_binX + bin * CAPX;

    // pass 1: mark + zero touched cells (all racing writes store 0 -> benign)
    for (int p = warp; p < cnt; p += 8) {
        int z = binp[p] & 511;
        if (lane == 0) atomicOr(&zmask[z >> 5], 1u << (z & 31));
        tile[z * ZPITCH + lane] = 0.f;
    }
    __syncthreads();

    // pass 2: accumulate
    for (int p = warp; p < cnt; p += 8) {
        int e  = binp[p];
        int pt = e >> 9;
        int z  = e & 511;
        float v = d_fbuf[(size_t)pt * C_OUT + c0 + lane];
        atomicAdd(&tile[z * ZPITCH + lane], v);
    }
    __syncthreads();

    // readout: out[b][c0+c][x][z], 32 rows of 512 floats, coalesced stores.
    float4* o4 = (float4*)(out + (((size_t)(b * C_OUT + c0)) * BEV_H + x) * BEV_W);
    for (int i = tid; i < 32 * 128; i += 256) {
        int c = i >> 7;                              // channel within group
        int j = i & 127;                             // 4-z chunk
        float4 v = make_float4(0.f, 0.f, 0.f, 0.f);
        unsigned int m = zmask[j >> 3];
        unsigned int bits = (m >> ((j & 7) * 4)) & 0xFu;
        if (bits) {
            int zb = 4 * j;
            if (bits & 1u) v.x = tile[(zb    ) * ZPITCH + c];
            if (bits & 2u) v.y = tile[(zb + 1) * ZPITCH + c];
            if (bits & 4u) v.z = tile[(zb + 2) * ZPITCH + c];
            if (bits & 8u) v.w = tile[(zb + 3) * ZPITCH + c];
        }
        __stcs(&o4[(size_t)c * (HW / 4) + j], v);
    }
}

// ---------------------------------------------------------------------------
// Launch
// ---------------------------------------------------------------------------
extern "C" void kernel_launch(void* const* d_in, const int* in_sizes, int n_in,
                              void* d_out, int out_size)
{
    const int*   coords = (const int*)  d_in[0];   // [N,4] int32
    const float* feats  = (const float*)d_in[1];   // [N,64] f32
    const float* kern   = (const float*)d_in[2];   // [16,64,128] f32
    float*       out    = (float*)d_out;           // [2,128,512,512] f32

    int n = in_sizes[0] / 4;
    if (n > MAXN) n = MAXN;

    k_zero<<<4, 256>>>();
    k_bin<<<(n + 255) / 256, 256>>>(coords, n);

    dim3 g1((n + PPB - 1) / PPB, NKER);
    k_feat<<<g1, 256>>>(feats, kern);

    dim3 g2(C_OUT / 32, NBX);
    k_bev<<<g2, 256>>>(out);
}

// round 5
// speedup vs baseline: 1.1200x; 1.1200x over previous
#include <cuda_runtime.h>

#define C_IN   64
#define C_OUT  128
#define NKER   16
#define BEV_H  512
#define BEV_W  512
#define HW     (BEV_H * BEV_W)
#define MAXN   65536
#define NBX    1024        // (b,x) bins
#define CAPX   1024        // max points per (b,x) bin (fixed region)
#define PPB    128         // points per block, phase 1
#define CG     16          // channels per k_bev block
#define ZPITCH 17          // z-major tile pitch (floats): 16 ch + 1 pad

// ---------------- scratch (__device__ globals; no allocation) ----------------
// Zero-initialized at module load; k_bev resets cursors after consuming them,
// so every kernel_launch execution starts from zeroed cursors (graph-safe).
__device__ int   d_curH[NKER];
__device__ int   d_curX[NBX];
__device__ int   d_binH[NKER * MAXN];            // point index, region per h
__device__ int   d_binX[NBX * CAPX];             // packed (pt << 9) | z
__device__ float d_fbuf[(size_t)MAXN * C_OUT];   // per-point features post-GEMM

// ---------------- packed f32x2 helpers ----------------
__device__ __forceinline__ unsigned long long pack2(float lo, float hi) {
    unsigned long long r;
    asm("mov.b64 %0, {%1, %2};" : "=l"(r) : "f"(lo), "f"(hi));
    return r;
}
__device__ __forceinline__ void unpack2(unsigned long long v, float& lo, float& hi) {
    asm("mov.b64 {%0, %1}, %2;" : "=f"(lo), "=f"(hi) : "l"(v));
}
__device__ __forceinline__ unsigned long long fma2(unsigned long long a,
                                                   unsigned long long b,
                                                   unsigned long long c) {
    unsigned long long d;
    asm("fma.rn.f32x2 %0, %1, %2, %3;" : "=l"(d) : "l"(a), "l"(b), "l"(c));
    return d;
}

// ---------------------------------------------------------------------------
// Fused binning: block-level smem histogram + rank, one global reservation
// per non-empty bin per block, then direct scatter into fixed bin regions.
// ---------------------------------------------------------------------------
__global__ __launch_bounds__(256)
void k_bin(const int* __restrict__ coords, int n)
{
    __shared__ int histH[NKER],  baseH[NKER];
    __shared__ int histX[NBX],   baseX[NBX];

    const int tid = threadIdx.x;
    for (int j = tid; j < NBX; j += 256) histX[j] = 0;
    if (tid < NKER) histH[tid] = 0;
    __syncthreads();

    int i = blockIdx.x * 256 + tid;
    int h = 0, bx = 0, z = 0, rH = 0, rX = 0;
    bool valid = (i < n);
    if (valid) {
        int4 c = ((const int4*)coords)[i];           // [x, h, z, b]
        h  = c.y & (NKER - 1);
        bx = (c.w << 9) | c.x;
        z  = c.z;
        rH = atomicAdd(&histH[h], 1);
        rX = atomicAdd(&histX[bx], 1);
    }
    __syncthreads();

    if (tid < NKER && histH[tid] > 0)
        baseH[tid] = atomicAdd(&d_curH[tid], histH[tid]);
    for (int j = tid; j < NBX; j += 256)
        if (histX[j] > 0)
            baseX[j] = atomicAdd(&d_curX[j], histX[j]);
    __syncthreads();

    if (valid) {
        d_binH[h * MAXN + baseH[h] + rH] = i;
        int slot = baseX[bx] + rX;
        if (slot < CAPX)
            d_binX[bx * CAPX + slot] = (i << 9) | z;
    }
}

// ---------------------------------------------------------------------------
// Phase 1: per-point GEMV  f_buf[pt][c] = sum_k feats[pt][k] * K[h][k][c]
// Block serves one h bin; 64x128 kernel slice staged in SMEM.
// Warp processes 4 points; lane owns 4 consecutive channels.
// Inner math on packed fma.rn.f32x2 (2 MACs / instr).
// ---------------------------------------------------------------------------
__global__ __launch_bounds__(256)
void k_feat(const float* __restrict__ feats,
            const float* __restrict__ kern)
{
    const int bin = blockIdx.y;
    const int cnt = d_curH[bin];
    const int bstart = blockIdx.x * PPB;
    if (bstart >= cnt) return;
    const int bend = min(bstart + PPB, cnt);
    const int* binp = d_binH + bin * MAXN;

    __shared__ float Ks[C_IN * C_OUT];               // 32 KB
    {
        const float4* g = (const float4*)(kern + (size_t)bin * C_IN * C_OUT);
        float4* sp = (float4*)Ks;
        for (int i = threadIdx.x; i < (C_IN * C_OUT) / 4; i += 256)
            sp[i] = g[i];
    }
    __syncthreads();

    const int warp = threadIdx.x >> 5;
    const int lane = threadIdx.x & 31;

    for (int g0 = bstart + warp * 4; g0 < bend; g0 += 32) {
        const int nv = min(4, bend - g0);
        float2 fv[4];
        int    pts[4];

        #pragma unroll
        for (int p = 0; p < 4; p++) {
            if (p < nv) {
                pts[p] = binp[g0 + p];
                fv[p]  = ((const float2*)(feats + (size_t)pts[p] * C_IN))[lane];
            } else {
                fv[p] = make_float2(0.f, 0.f);
                pts[p] = 0;
            }
        }

        unsigned long long accA[4], accB[4];
        #pragma unroll
        for (int p = 0; p < 4; p++) { accA[p] = 0ull; accB[p] = 0ull; }

        #pragma unroll
        for (int c = 0; c < C_IN; c++) {
            float4 k = *(const float4*)(Ks + c * C_OUT + 4 * lane);
            unsigned long long kA = pack2(k.x, k.y);
            unsigned long long kB = pack2(k.z, k.w);
            #pragma unroll
            for (int p = 0; p < 4; p++) {
                float f = __shfl_sync(0xffffffffu,
                                      (c & 1) ? fv[p].y : fv[p].x, c >> 1);
                unsigned long long ff = pack2(f, f);
                accA[p] = fma2(ff, kA, accA[p]);
                accB[p] = fma2(ff, kB, accB[p]);
            }
        }

        #pragma unroll
        for (int p = 0; p < 4; p++) {
            if (p < nv) {
                float4 v;
                unpack2(accA[p], v.x, v.y);
                unpack2(accB[p], v.z, v.w);
                *(float4*)(d_fbuf + (size_t)pts[p] * C_OUT + 4 * lane) = v;
            }
        }
    }
}

// ---------------------------------------------------------------------------
// Phase 2: row-owner scatter with sparse tile, 16 channels per block.
// Block = (channel group of 16, bin (b,x)). Tile z-major [512][17]:
// half-warp scatters one point's 16 channels conflict-free.
// 34.8 KB smem -> 6 blocks/SM for latency hiding.
// Pass 1 marks touched z + zeroes touched cells; pass 2 smem-atomic adds;
// readout stores register zeros for untouched 4-z chunks (~92%).
// All 8192 blocks together overwrite every output element -> no memset.
// Cursor reset at the end keeps device state zeroed for the next replay.
// ---------------------------------------------------------------------------
__global__ __launch_bounds__(256)
void k_bev(float* __restrict__ out)
{
    __shared__ float tile[512 * ZPITCH];             // 34.8 KB
    __shared__ unsigned int zmask[16];               // 512 bits

    const int bin = blockIdx.y;
    const int c0  = blockIdx.x << 4;
    const int b   = bin >> 9;
    const int x   = bin & 511;
    const int tid  = threadIdx.x;
    const int hwid = tid >> 4;                       // half-warp id, 0..15
    const int hl   = tid & 15;                       // lane within half-warp

    if (tid < 16) zmask[tid] = 0u;
    __syncthreads();

    int cnt = d_curX[bin];
    if (cnt > CAPX) cnt = CAPX;
    const int* binp = d_binX + bin * CAPX;

    // pass 1: mark + zero touched cells (races write 0 -> benign)
    for (int p = hwid; p < cnt; p += 16) {
        int z = binp[p] & 511;
        if (hl == 0) atomicOr(&zmask[z >> 5], 1u << (z & 31));
        tile[z * ZPITCH + hl] = 0.f;
    }
    __syncthreads();

    // pass 2: accumulate (half-warp = one point, lane = channel)
    for (int p = hwid; p < cnt; p += 16) {
        int e  = binp[p];
        int pt = e >> 9;
        int z  = e & 511;
        float v = d_fbuf[(size_t)pt * C_OUT + c0 + hl];
        atomicAdd(&tile[z * ZPITCH + hl], v);
    }
    __syncthreads();

    // readout: out[b][c0+c][x][z], 16 rows of 512 floats, coalesced stores.
    float4* o4 = (float4*)(out + (((size_t)(b * C_OUT + c0)) * BEV_H + x) * BEV_W);
    #pragma unroll
    for (int i = tid; i < CG * 128; i += 256) {
        int c = i >> 7;                              // channel within group
        int j = i & 127;                             // 4-z chunk
        float4 v = make_float4(0.f, 0.f, 0.f, 0.f);
        unsigned int m = zmask[j >> 3];
        unsigned int bits = (m >> ((j & 7) * 4)) & 0xFu;
        if (bits) {
            int zb = 4 * j;
            if (bits & 1u) v.x = tile[(zb    ) * ZPITCH + c];
            if (bits & 2u) v.y = tile[(zb + 1) * ZPITCH + c];
            if (bits & 4u) v.z = tile[(zb + 2) * ZPITCH + c];
            if (bits & 8u) v.w = tile[(zb + 3) * ZPITCH + c];
        }
        __stcs(&o4[(size_t)c * (HW / 4) + j], v);
    }

    // reset cursors for the next graph replay
    if (tid == 0 && blockIdx.x == 0) {
        d_curX[bin] = 0;
        if (bin < NKER) d_curH[bin] = 0;
    }
}

// ---------------------------------------------------------------------------
// Launch
// ---------------------------------------------------------------------------
extern "C" void kernel_launch(void* const* d_in, const int* in_sizes, int n_in,
                              void* d_out, int out_size)
{
    const int*   coords = (const int*)  d_in[0];   // [N,4] int32
    const float* feats  = (const float*)d_in[1];   // [N,64] f32
    const float* kern   = (const float*)d_in[2];   // [16,64,128] f32
    float*       out    = (float*)d_out;           // [2,128,512,512] f32

    int n = in_sizes[0] / 4;
    if (n > MAXN) n = MAXN;

    k_bin<<<(n + 255) / 256, 256>>>(coords, n);

    dim3 g1((n + PPB - 1) / PPB, NKER);
    k_feat<<<g1, 256>>>(feats, kern);

    dim3 g2(C_OUT / CG, NBX);
    k_bev<<<g2, 256>>>(out);
}

// round 6
// speedup vs baseline: 1.2122x; 1.0824x over previous
#include <cuda_runtime.h>

#define C_IN   64
#define C_OUT  128
#define NKER   16
#define BEV_H  512
#define BEV_W  512
#define HW     (BEV_H * BEV_W)
#define MAXN   65536
#define NBX    1024        // (b,x) bins
#define CAPX   1024        // max points per (b,x) bin (fixed region)
#define PPB    64          // points per block, phase 1
#define CG     8           // channels per k_bev block
#define ZPITCH 9           // z-major tile pitch (floats): 8 ch + 1 pad

// ---------------- scratch (__device__ globals; no allocation) ----------------
// Zero-initialized at module load; k_bev resets cursors after consuming them,
// so every kernel_launch execution starts from zeroed cursors (graph-safe).
__device__ int   d_curH[NKER];
__device__ int   d_curX[NBX];
__device__ int   d_binH[NKER * MAXN];            // point index, region per h
__device__ int   d_binX[NBX * CAPX];             // packed (pt << 9) | z
__device__ float d_fbuf[(size_t)MAXN * C_OUT];   // per-point features post-GEMM

// ---------------- packed f32x2 helpers ----------------
__device__ __forceinline__ unsigned long long pack2(float lo, float hi) {
    unsigned long long r;
    asm("mov.b64 %0, {%1, %2};" : "=l"(r) : "f"(lo), "f"(hi));
    return r;
}
__device__ __forceinline__ void unpack2(unsigned long long v, float& lo, float& hi) {
    asm("mov.b64 {%0, %1}, %2;" : "=f"(lo), "=f"(hi) : "l"(v));
}
__device__ __forceinline__ unsigned long long fma2(unsigned long long a,
                                                   unsigned long long b,
                                                   unsigned long long c) {
    unsigned long long d;
    asm("fma.rn.f32x2 %0, %1, %2, %3;" : "=l"(d) : "l"(a), "l"(b), "l"(c));
    return d;
}

// ---------------------------------------------------------------------------
// Fused binning: block-level smem histogram + rank, one global reservation
// per non-empty bin per block, then direct scatter into fixed bin regions.
// ---------------------------------------------------------------------------
__global__ __launch_bounds__(256)
void k_bin(const int* __restrict__ coords, int n)
{
    __shared__ int histH[NKER],  baseH[NKER];
    __shared__ int histX[NBX],   baseX[NBX];

    const int tid = threadIdx.x;
    for (int j = tid; j < NBX; j += 256) histX[j] = 0;
    if (tid < NKER) histH[tid] = 0;
    __syncthreads();

    int i = blockIdx.x * 256 + tid;
    int h = 0, bx = 0, z = 0, rH = 0, rX = 0;
    bool valid = (i < n);
    if (valid) {
        int4 c = ((const int4*)coords)[i];           // [x, h, z, b]
        h  = c.y & (NKER - 1);
        bx = (c.w << 9) | c.x;
        z  = c.z;
        rH = atomicAdd(&histH[h], 1);
        rX = atomicAdd(&histX[bx], 1);
    }
    __syncthreads();

    if (tid < NKER && histH[tid] > 0)
        baseH[tid] = atomicAdd(&d_curH[tid], histH[tid]);
    for (int j = tid; j < NBX; j += 256)
        if (histX[j] > 0)
            baseX[j] = atomicAdd(&d_curX[j], histX[j]);
    __syncthreads();

    if (valid) {
        d_binH[h * MAXN + baseH[h] + rH] = i;
        int slot = baseX[bx] + rX;
        if (slot < CAPX)
            d_binX[bx * CAPX + slot] = (i << 9) | z;
    }
}

// ---------------------------------------------------------------------------
// Phase 1: per-point GEMV  f_buf[pt][c] = sum_k feats[pt][k] * K[h][k][c]
// Block serves one h bin; 64x128 kernel slice staged in SMEM.
// Warp processes 4 points; lane owns 4 consecutive channels.
// Inner math on packed fma.rn.f32x2 (2 MACs / instr).
// ---------------------------------------------------------------------------
__global__ __launch_bounds__(256)
void k_feat(const float* __restrict__ feats,
            const float* __restrict__ kern)
{
    const int bin = blockIdx.y;
    const int cnt = d_curH[bin];
    const int bstart = blockIdx.x * PPB;
    if (bstart >= cnt) return;
    const int bend = min(bstart + PPB, cnt);
    const int* binp = d_binH + bin * MAXN;

    __shared__ float Ks[C_IN * C_OUT];               // 32 KB
    {
        const float4* g = (const float4*)(kern + (size_t)bin * C_IN * C_OUT);
        float4* sp = (float4*)Ks;
        for (int i = threadIdx.x; i < (C_IN * C_OUT) / 4; i += 256)
            sp[i] = g[i];
    }
    __syncthreads();

    const int warp = threadIdx.x >> 5;
    const int lane = threadIdx.x & 31;

    for (int g0 = bstart + warp * 4; g0 < bend; g0 += 32) {
        const int nv = min(4, bend - g0);
        float2 fv[4];
        int    pts[4];

        #pragma unroll
        for (int p = 0; p < 4; p++) {
            if (p < nv) {
                pts[p] = binp[g0 + p];
                fv[p]  = ((const float2*)(feats + (size_t)pts[p] * C_IN))[lane];
            } else {
                fv[p] = make_float2(0.f, 0.f);
                pts[p] = 0;
            }
        }

        unsigned long long accA[4], accB[4];
        #pragma unroll
        for (int p = 0; p < 4; p++) { accA[p] = 0ull; accB[p] = 0ull; }

        #pragma unroll
        for (int c = 0; c < C_IN; c++) {
            float4 k = *(const float4*)(Ks + c * C_OUT + 4 * lane);
            unsigned long long kA = pack2(k.x, k.y);
            unsigned long long kB = pack2(k.z, k.w);
            #pragma unroll
            for (int p = 0; p < 4; p++) {
                float f = __shfl_sync(0xffffffffu,
                                      (c & 1) ? fv[p].y : fv[p].x, c >> 1);
                unsigned long long ff = pack2(f, f);
                accA[p] = fma2(ff, kA, accA[p]);
                accB[p] = fma2(ff, kB, accB[p]);
            }
        }

        #pragma unroll
        for (int p = 0; p < 4; p++) {
            if (p < nv) {
                float4 v;
                unpack2(accA[p], v.x, v.y);
                unpack2(accB[p], v.z, v.w);
                *(float4*)(d_fbuf + (size_t)pts[p] * C_OUT + 4 * lane) = v;
            }
        }
    }
}

// ---------------------------------------------------------------------------
// Phase 2: row-owner scatter with sparse tile, 8 channels per block.
// Block = (channel group of 8, bin (b,x)). Tile z-major [512][9]:
// quarter-warp scatters one point's 8 channels conflict-free within group.
// 18.4 KB smem -> 8 blocks/SM (64 warps, FULL occupancy).
// Pass 1 marks touched z + zeroes touched cells; pass 2 smem-atomic adds;
// readout stores register zeros for untouched 4-z chunks (~92%).
// All 16384 blocks together overwrite every output element -> no memset.
// Cursor reset at the end keeps device state zeroed for the next replay.
// ---------------------------------------------------------------------------
__global__ __launch_bounds__(256)
void k_bev(float* __restrict__ out)
{
    __shared__ float tile[512 * ZPITCH];             // 18.4 KB
    __shared__ unsigned int zmask[16];               // 512 bits

    const int bin = blockIdx.y;
    const int c0  = blockIdx.x << 3;
    const int b   = bin >> 9;
    const int x   = bin & 511;
    const int tid  = threadIdx.x;
    const int qwid = tid >> 3;                       // quarter-warp id, 0..31
    const int ql   = tid & 7;                        // lane within group

    if (tid < 16) zmask[tid] = 0u;
    __syncthreads();

    int cnt = d_curX[bin];
    if (cnt > CAPX) cnt = CAPX;
    const int* binp = d_binX + bin * CAPX;

    // pass 1: mark + zero touched cells (races write 0 -> benign)
    for (int p = qwid; p < cnt; p += 32) {
        int z = binp[p] & 511;
        if (ql == 0) atomicOr(&zmask[z >> 5], 1u << (z & 31));
        tile[z * ZPITCH + ql] = 0.f;
    }
    __syncthreads();

    // pass 2: accumulate (quarter-warp = one point, lane = channel)
    for (int p = qwid; p < cnt; p += 32) {
        int e  = binp[p];
        int pt = e >> 9;
        int z  = e & 511;
        float v = d_fbuf[(size_t)pt * C_OUT + c0 + ql];
        atomicAdd(&tile[z * ZPITCH + ql], v);
    }
    __syncthreads();

    // readout: out[b][c0+c][x][z], 8 rows of 512 floats, coalesced stores.
    float4* o4 = (float4*)(out + (((size_t)(b * C_OUT + c0)) * BEV_H + x) * BEV_W);
    #pragma unroll
    for (int i = tid; i < CG * 128; i += 256) {
        int c = i >> 7;                              // channel within group
        int j = i & 127;                             // 4-z chunk
        float4 v = make_float4(0.f, 0.f, 0.f, 0.f);
        unsigned int m = zmask[j >> 3];
        unsigned int bits = (m >> ((j & 7) * 4)) & 0xFu;
        if (bits) {
            int zb = 4 * j;
            if (bits & 1u) v.x = tile[(zb    ) * ZPITCH + c];
            if (bits & 2u) v.y = tile[(zb + 1) * ZPITCH + c];
            if (bits & 4u) v.z = tile[(zb + 2) * ZPITCH + c];
            if (bits & 8u) v.w = tile[(zb + 3) * ZPITCH + c];
        }
        __stcs(&o4[(size_t)c * (HW / 4) + j], v);
    }

    // reset cursors for the next graph replay
    if (tid == 0 && blockIdx.x == 0) {
        d_curX[bin] = 0;
        if (bin < NKER) d_curH[bin] = 0;
    }
}

// ---------------------------------------------------------------------------
// Launch
// ---------------------------------------------------------------------------
extern "C" void kernel_launch(void* const* d_in, const int* in_sizes, int n_in,
                              void* d_out, int out_size)
{
    const int*   coords = (const int*)  d_in[0];   // [N,4] int32
    const float* feats  = (const float*)d_in[1];   // [N,64] f32
    const float* kern   = (const float*)d_in[2];   // [16,64,128] f32
    float*       out    = (float*)d_out;           // [2,128,512,512] f32

    int n = in_sizes[0] / 4;
    if (n > MAXN) n = MAXN;

    k_bin<<<(n + 255) / 256, 256>>>(coords, n);

    dim3 g1((n + PPB - 1) / PPB, NKER);
    k_feat<<<g1, 256>>>(feats, kern);

    dim3 g2(C_OUT / CG, NBX);
    k_bev<<<g2, 256>>>(out);
}

// round 7
// speedup vs baseline: 1.3421x; 1.1071x over previous
#include <cuda_runtime.h>

#define C_IN   64
#define C_OUT  128
#define NKER   16
#define BEV_H  512
#define BEV_W  512
#define HW     (BEV_H * BEV_W)
#define MAXN   65536
#define NBX    1024        // (b,x) bins
#define CAPX   1024        // max points per (b,x) bin (fixed region)
#define PPB    64          // points per chunk, phase 1
#define FBLK   40          // k_feat blocks per h bin (grid-strided)
#define CG     8           // channels per k_bev block
#define ZPITCH 9           // z-major tile pitch (floats): 8 ch + 1 pad

// ---------------- scratch (__device__ globals; no allocation) ----------------
// Zero-initialized at module load; k_bev resets cursors after consuming them,
// so every kernel_launch execution starts from zeroed cursors (graph-safe).
__device__ int   d_curH[NKER];
__device__ int   d_curX[NBX];
__device__ int   d_binH[NKER * MAXN];            // point index, region per h
__device__ int   d_binX[NBX * CAPX];             // packed (pt << 9) | z
__device__ float d_fbuf[(size_t)MAXN * C_OUT];   // per-point features post-GEMM

// ---------------- packed f32x2 helpers ----------------
__device__ __forceinline__ unsigned long long pack2(float lo, float hi) {
    unsigned long long r;
    asm("mov.b64 %0, {%1, %2};" : "=l"(r) : "f"(lo), "f"(hi));
    return r;
}
__device__ __forceinline__ void unpack2(unsigned long long v, float& lo, float& hi) {
    asm("mov.b64 {%0, %1}, %2;" : "=f"(lo), "=f"(hi) : "l"(v));
}
__device__ __forceinline__ unsigned long long fma2(unsigned long long a,
                                                   unsigned long long b,
                                                   unsigned long long c) {
    unsigned long long d;
    asm("fma.rn.f32x2 %0, %1, %2, %3;" : "=l"(d) : "l"(a), "l"(b), "l"(c));
    return d;
}

// ---------------------------------------------------------------------------
// Fused binning: block-level smem histogram + rank, one global reservation
// per non-empty bin per block, then direct scatter into fixed bin regions.
// ---------------------------------------------------------------------------
__global__ __launch_bounds__(256)
void k_bin(const int* __restrict__ coords, int n)
{
    __shared__ int histH[NKER],  baseH[NKER];
    __shared__ int histX[NBX],   baseX[NBX];

    const int tid = threadIdx.x;
    {
        int4* h4 = (int4*)histX;
        h4[tid] = make_int4(0, 0, 0, 0);             // 256 int4 = 1024 ints
    }
    if (tid < NKER) histH[tid] = 0;
    __syncthreads();

    int i = blockIdx.x * 256 + tid;
    int h = 0, bx = 0, z = 0, rH = 0, rX = 0;
    bool valid = (i < n);
    if (valid) {
        int4 c = ((const int4*)coords)[i];           // [x, h, z, b]
        h  = c.y & (NKER - 1);
        bx = (c.w << 9) | c.x;
        z  = c.z;
        rH = atomicAdd(&histH[h], 1);
        rX = atomicAdd(&histX[bx], 1);
    }
    __syncthreads();

    if (tid < NKER && histH[tid] > 0)
        baseH[tid] = atomicAdd(&d_curH[tid], histH[tid]);
    for (int j = tid; j < NBX; j += 256)
        if (histX[j] > 0)
            baseX[j] = atomicAdd(&d_curX[j], histX[j]);
    __syncthreads();

    if (valid) {
        d_binH[h * MAXN + baseH[h] + rH] = i;
        int slot = baseX[bx] + rX;
        if (slot < CAPX)
            d_binX[bx * CAPX + slot] = (i << 9) | z;
    }
    cudaTriggerProgrammaticLaunchCompletion();
}

// ---------------------------------------------------------------------------
// Phase 1: per-point GEMV  f_buf[pt][c] = sum_k feats[pt][k] * K[h][k][c]
// Grid (FBLK, NKER), grid-strided over the bin's points so every block is
// productive. Kernel slice is staged into SMEM BEFORE the PDL grid sync,
// overlapping with k_bin's tail.
// ---------------------------------------------------------------------------
__global__ __launch_bounds__(256)
void k_feat(const float* __restrict__ feats,
            const float* __restrict__ kern)
{
    const int bin = blockIdx.y;

    __shared__ float Ks[C_IN * C_OUT];               // 32 KB
    {
        const float4* g = (const float4*)(kern + (size_t)bin * C_IN * C_OUT);
        float4* sp = (float4*)Ks;
        for (int i = threadIdx.x; i < (C_IN * C_OUT) / 4; i += 256)
            sp[i] = g[i];
    }

    cudaGridDependencySynchronize();                 // wait for k_bin results
    __syncthreads();

    const int cnt = d_curH[bin];
    const int* binp = d_binH + bin * MAXN;
    const int warp = threadIdx.x >> 5;
    const int lane = threadIdx.x & 31;

    for (int bstart = blockIdx.x * PPB; bstart < cnt; bstart += FBLK * PPB) {
        const int bend = min(bstart + PPB, cnt);

        for (int g0 = bstart + warp * 4; g0 < bend; g0 += 32) {
            const int nv = min(4, bend - g0);
            float2 fv[4];
            int    pts[4];

            #pragma unroll
            for (int p = 0; p < 4; p++) {
                if (p < nv) {
                    pts[p] = binp[g0 + p];
                    fv[p]  = ((const float2*)(feats + (size_t)pts[p] * C_IN))[lane];
                } else {
                    fv[p] = make_float2(0.f, 0.f);
                    pts[p] = 0;
                }
            }

            unsigned long long accA[4], accB[4];
            #pragma unroll
            for (int p = 0; p < 4; p++) { accA[p] = 0ull; accB[p] = 0ull; }

            #pragma unroll
            for (int c = 0; c < C_IN; c++) {
                float4 k = *(const float4*)(Ks + c * C_OUT + 4 * lane);
                unsigned long long kA = pack2(k.x, k.y);
                unsigned long long kB = pack2(k.z, k.w);
                #pragma unroll
                for (int p = 0; p < 4; p++) {
                    float f = __shfl_sync(0xffffffffu,
                                          (c & 1) ? fv[p].y : fv[p].x, c >> 1);
                    unsigned long long ff = pack2(f, f);
                    accA[p] = fma2(ff, kA, accA[p]);
                    accB[p] = fma2(ff, kB, accB[p]);
                }
            }

            #pragma unroll
            for (int p = 0; p < 4; p++) {
                if (p < nv) {
                    float4 v;
                    unpack2(accA[p], v.x, v.y);
                    unpack2(accB[p], v.z, v.w);
                    *(float4*)(d_fbuf + (size_t)pts[p] * C_OUT + 4 * lane) = v;
                }
            }
        }
    }
    cudaTriggerProgrammaticLaunchCompletion();
}

// ---------------------------------------------------------------------------
// Phase 2: row-owner scatter with sparse tile, 8 channels per block.
// PDL: pass 1 (zmask + touched-cell zeroing) only needs d_binX/d_curX, which
// are complete before this grid can start (transitively via k_feat's grid
// sync); the PDL grid sync is deferred until just before pass 2 reads f_buf.
// ---------------------------------------------------------------------------
__global__ __launch_bounds__(256)
void k_bev(float* __restrict__ out)
{
    __shared__ float tile[512 * ZPITCH];             // 18.4 KB
    __shared__ unsigned int zmask[16];               // 512 bits

    const int bin = blockIdx.y;
    const int c0  = blockIdx.x << 3;
    const int b   = bin >> 9;
    const int x   = bin & 511;
    const int tid  = threadIdx.x;
    const int qwid = tid >> 3;                       // quarter-warp id, 0..31
    const int ql   = tid & 7;                        // lane within group

    if (tid < 16) zmask[tid] = 0u;
    __syncthreads();

    int cnt = d_curX[bin];
    if (cnt > CAPX) cnt = CAPX;
    const int* binp = d_binX + bin * CAPX;

    // pass 1: mark + zero touched cells (races write 0 -> benign)
    for (int p = qwid; p < cnt; p += 32) {
        int z = binp[p] & 511;
        if (ql == 0) atomicOr(&zmask[z >> 5], 1u << (z & 31));
        tile[z * ZPITCH + ql] = 0.f;
    }

    cudaGridDependencySynchronize();                 // wait for k_feat's f_buf
    __syncthreads();

    // pass 2: accumulate (quarter-warp = one point, lane = channel)
    for (int p = qwid; p < cnt; p += 32) {
        int e  = binp[p];
        int pt = e >> 9;
        int z  = e & 511;
        float v = d_fbuf[(size_t)pt * C_OUT + c0 + ql];
        atomicAdd(&tile[z * ZPITCH + ql], v);
    }
    __syncthreads();

    // readout: out[b][c0+c][x][z], 8 rows of 512 floats, coalesced stores.
    float4* o4 = (float4*)(out + (((size_t)(b * C_OUT + c0)) * BEV_H + x) * BEV_W);
    #pragma unroll
    for (int i = tid; i < CG * 128; i += 256) {
        int c = i >> 7;                              // channel within group
        int j = i & 127;                             // 4-z chunk
        float4 v = make_float4(0.f, 0.f, 0.f, 0.f);
        unsigned int m = zmask[j >> 3];
        unsigned int bits = (m >> ((j & 7) * 4)) & 0xFu;
        if (bits) {
            int zb = 4 * j;
            if (bits & 1u) v.x = tile[(zb    ) * ZPITCH + c];
            if (bits & 2u) v.y = tile[(zb + 1) * ZPITCH + c];
            if (bits & 4u) v.z = tile[(zb + 2) * ZPITCH + c];
            if (bits & 8u) v.w = tile[(zb + 3) * ZPITCH + c];
        }
        __stcs(&o4[(size_t)c * (HW / 4) + j], v);
    }

    // reset cursors for the next graph replay
    if (tid == 0 && blockIdx.x == 0) {
        d_curX[bin] = 0;
        if (bin < NKER) d_curH[bin] = 0;
    }
}

// ---------------------------------------------------------------------------
// Launch (PDL chain: k_bin -> k_feat -> k_bev)
// ---------------------------------------------------------------------------
extern "C" void kernel_launch(void* const* d_in, const int* in_sizes, int n_in,
                              void* d_out, int out_size)
{
    const int*   coords = (const int*)  d_in[0];   // [N,4] int32
    const float* feats  = (const float*)d_in[1];   // [N,64] f32
    const float* kern   = (const float*)d_in[2];   // [16,64,128] f32
    float*       out    = (float*)d_out;           // [2,128,512,512] f32

    int n = in_sizes[0] / 4;
    if (n > MAXN) n = MAXN;

    k_bin<<<(n + 255) / 256, 256>>>(coords, n);

    cudaLaunchAttribute attrs[1];
    attrs[0].id = cudaLaunchAttributeProgrammaticStreamSerialization;
    attrs[0].val.programmaticStreamSerializationAllowed = 1;

    {   // k_feat with PDL
        cudaLaunchConfig_t cfg = {};
        cfg.gridDim  = dim3(FBLK, NKER);
        cfg.blockDim = dim3(256);
        cfg.stream   = 0;
        cfg.attrs    = attrs;
        cfg.numAttrs = 1;
        cudaLaunchKernelEx(&cfg, k_feat, feats, kern);
    }
    {   // k_bev with PDL
        cudaLaunchConfig_t cfg = {};
        cfg.gridDim  = dim3(C_OUT / CG, NBX);
        cfg.blockDim = dim3(256);
        cfg.stream   = 0;
        cfg.attrs    = attrs;
        cfg.numAttrs = 1;
        cudaLaunchKernelEx(&cfg, k_bev, out);
    }
}